// round 5
// baseline (speedup 1.0000x reference)
#include <cuda_runtime.h>
#include <cuda_fp16.h>
#include <cstddef>

// Problem constants (fixed by the reference)
#define B_    4096
#define NIN_  512
#define L_    16
#define N_    512
#define K_    32
#define NOUT_ 256
#define TOTAL_ (NIN_ + L_ * N_)   // 8704

// x buffer, transposed fp16: g_x16[f * B + b], f in [0, NIN)   (~4 MB)
__device__ __half g_x16[(size_t)NIN_ * B_];
// hidden activations, transposed uint8: g_act8[(f-NIN) * B + b] (~33.5 MB)
__device__ unsigned char g_act8[(size_t)(L_ * N_) * B_];

__device__ __forceinline__ float sigmoidf_(float v) {
    return 1.0f / (1.0f + __expf(-v));
}

// acc[0..7] += w * 8 halves
__device__ __forceinline__ void fma8h_(float* a, float w, uint4 v) {
    const unsigned* vw = &v.x;
#pragma unroll
    for (int i = 0; i < 4; ++i) {
        __half2 h = *reinterpret_cast<const __half2*>(&vw[i]);
        float2 f = __half22float2(h);
        a[2 * i]     = fmaf(w, f.x, a[2 * i]);
        a[2 * i + 1] = fmaf(w, f.y, a[2 * i + 1]);
    }
}

// acc[0..15] += wc * 16 uint8s
__device__ __forceinline__ void fma16b_(float* a, float wc, uint4 v) {
    const unsigned* vw = &v.x;
#pragma unroll
    for (int i = 0; i < 4; ++i) {
        const unsigned word = vw[i];
        a[4 * i + 0] = fmaf(wc, (float)(word & 0xFFu),         a[4 * i + 0]);
        a[4 * i + 1] = fmaf(wc, (float)((word >> 8) & 0xFFu),  a[4 * i + 1]);
        a[4 * i + 2] = fmaf(wc, (float)((word >> 16) & 0xFFu), a[4 * i + 2]);
        a[4 * i + 3] = fmaf(wc, (float)(word >> 24),           a[4 * i + 3]);
    }
}

// Gather-accumulate 16 batch elems for one k (warp-uniform branch on f)
__device__ __forceinline__ void gather_fma_(float* a, int f, float w, int q) {
    if (f < NIN_) {
        const uint4* xv = reinterpret_cast<const uint4*>(g_x16);
        const size_t base = (size_t)f * (B_ / 8) + 2 * q;
        uint4 v0 = xv[base];
        uint4 v1 = xv[base + 1];
        fma8h_(a,     w, v0);
        fma8h_(a + 8, w, v1);
    } else {
        const uint4* av = reinterpret_cast<const uint4*>(g_act8);
        uint4 v = av[(size_t)(f - NIN_) * (B_ / 16) + q];
        fma16b_(a, w * (1.0f / 255.0f), v);
    }
}

// ---------------------------------------------------------------------------
// Transpose x (B, NIN) f32 row-major -> g_x16[f * B + b] as half
// ---------------------------------------------------------------------------
__global__ void __launch_bounds__(1024) transpose_in_kernel(const float* __restrict__ x) {
    __shared__ float tile[32][33];
    int f0 = blockIdx.x * 32;
    int b0 = blockIdx.y * 32;
    tile[threadIdx.y][threadIdx.x] = x[(size_t)(b0 + threadIdx.y) * NIN_ + (f0 + threadIdx.x)];
    __syncthreads();
    g_x16[(size_t)(f0 + threadIdx.y) * B_ + (b0 + threadIdx.x)] =
        __float2half(tile[threadIdx.x][threadIdx.y]);
}

// ---------------------------------------------------------------------------
// One sparse layer. block (32,8): 8 neurons x 512 batch (16 per thread).
// grid: (8, 64) = 512 blocks.
// ---------------------------------------------------------------------------
__global__ void __launch_bounds__(256, 4) layer_kernel(
    const float* __restrict__ W,     // (N, K) this layer
    const float* __restrict__ bias,  // (N,)
    const int*   __restrict__ idx,   // (N, K)
    int l)                           // layer index
{
    __shared__ int2 s_iw[8][K_];
    const int tx = threadIdx.x, ty = threadIdx.y;
    const int n = blockIdx.y * 8 + ty;

    {
        int2 p;
        p.x = idx[n * K_ + tx];
        p.y = __float_as_int(W[n * K_ + tx]);
        s_iw[ty][tx] = p;
    }
    __syncthreads();

    const int q = blockIdx.x * 32 + tx;   // batch chunk [16q, 16q+16)

    float a[16];
#pragma unroll
    for (int i = 0; i < 16; ++i) a[i] = 0.f;

#pragma unroll
    for (int k = 0; k < K_; ++k) {
        const int2 iw = s_iw[ty][k];
        gather_fma_(a, iw.x, __int_as_float(iw.y), q);
    }

    const float bb = bias[n];
    uint4 o;
    unsigned* ow = &o.x;
#pragma unroll
    for (int i = 0; i < 4; ++i) {
        unsigned b0 = __float2uint_rn(sigmoidf_(a[4 * i + 0] + bb) * 255.f);
        unsigned b1 = __float2uint_rn(sigmoidf_(a[4 * i + 1] + bb) * 255.f);
        unsigned b2 = __float2uint_rn(sigmoidf_(a[4 * i + 2] + bb) * 255.f);
        unsigned b3 = __float2uint_rn(sigmoidf_(a[4 * i + 3] + bb) * 255.f);
        ow[i] = b0 | (b1 << 8) | (b2 << 16) | (b3 << 24);
    }
    reinterpret_cast<uint4*>(g_act8)[(size_t)(l * N_ + n) * (B_ / 16) + q] = o;
}

// ---------------------------------------------------------------------------
// Output layer. block (32,8): 8 neurons x 512 batch (16 per thread).
// grid: (8, 32) = 256 blocks. smem-transpose for 32B-sector stores.
// ---------------------------------------------------------------------------
__global__ void __launch_bounds__(256) out_kernel(
    const float* __restrict__ W_out,   // (NOUT, K)
    const float* __restrict__ b_out,   // (NOUT,)
    const int*   __restrict__ idx_out, // (NOUT, K)
    float* __restrict__ out)           // (B, NOUT)
{
    __shared__ int2  s_iw[8][K_];
    __shared__ float tile[8][512];     // [neuron][batch within block]
    const int tx = threadIdx.x, ty = threadIdx.y;
    const int o0 = blockIdx.y * 8;
    const int o = o0 + ty;

    {
        int2 p;
        p.x = idx_out[o * K_ + tx];
        p.y = __float_as_int(W_out[o * K_ + tx]);
        s_iw[ty][tx] = p;
    }
    __syncthreads();

    const int q = blockIdx.x * 32 + tx;

    float a[16];
#pragma unroll
    for (int i = 0; i < 16; ++i) a[i] = 0.f;

#pragma unroll
    for (int k = 0; k < K_; ++k) {
        const int2 iw = s_iw[ty][k];
        gather_fma_(a, iw.x, __int_as_float(iw.y), q);
    }

    const float bb = b_out[o];
    const int bl = tx * 16;
#pragma unroll
    for (int i = 0; i < 16; ++i) tile[ty][bl + i] = sigmoidf_(a[i] + bb);
    __syncthreads();

    // 512 local batch rows, 256 threads -> 2 rows each, 8 f32 (two 16B) per row
    const int t = ty * 32 + tx;
    const int bbase = blockIdx.x * 512;
#pragma unroll
    for (int r = 0; r < 2; ++r) {
        const int lb = t + r * 256;
        float4 w0, w1;
        w0.x = tile[0][lb]; w0.y = tile[1][lb]; w0.z = tile[2][lb]; w0.w = tile[3][lb];
        w1.x = tile[4][lb]; w1.y = tile[5][lb]; w1.z = tile[6][lb]; w1.w = tile[7][lb];
        float4* dst = reinterpret_cast<float4*>(out + (size_t)(bbase + lb) * NOUT_ + o0);
        dst[0] = w0;
        dst[1] = w1;
    }
}

// ---------------------------------------------------------------------------
// kernel_launch: inputs in metadata order:
//   0: x (B,NIN) f32   1: W (L,N,K) f32   2: b (L,N) f32
//   3: W_out (NOUT,K) f32   4: b_out (NOUT,) f32
//   5: idx (L,N,K) i32      6: idx_out (NOUT,K) i32
// ---------------------------------------------------------------------------
extern "C" void kernel_launch(void* const* d_in, const int* in_sizes, int n_in,
                              void* d_out, int out_size) {
    const float* x     = (const float*)d_in[0];
    const float* W     = (const float*)d_in[1];
    const float* b     = (const float*)d_in[2];
    const float* W_out = (const float*)d_in[3];
    const float* b_out = (const float*)d_in[4];
    const int*   idx     = (const int*)d_in[5];
    const int*   idx_out = (const int*)d_in[6];
    float* out = (float*)d_out;

    {
        dim3 blk(32, 32);
        dim3 grd(NIN_ / 32, B_ / 32);
        transpose_in_kernel<<<grd, blk>>>(x);
    }
    {
        dim3 blk(32, 8);
        dim3 grd(8, N_ / 8);
        for (int l = 0; l < L_; ++l) {
            layer_kernel<<<grd, blk>>>(W + (size_t)l * N_ * K_,
                                       b + (size_t)l * N_,
                                       idx + (size_t)l * N_ * K_,
                                       l);
        }
    }
    {
        dim3 blk(32, 8);
        dim3 grd(8, NOUT_ / 8);
        out_kernel<<<grd, blk>>>(W_out, b_out, idx_out, out);
    }
}

// round 6
// speedup vs baseline: 1.3091x; 1.3091x over previous
#include <cuda_runtime.h>
#include <cuda_fp16.h>
#include <cstddef>

// Problem constants (fixed by the reference)
#define B_    4096
#define NIN_  512
#define L_    16
#define N_    512
#define K_    32
#define NOUT_ 256
#define TOTAL_ (NIN_ + L_ * N_)   // 8704

// x buffer, transposed fp16: g_x16[f * B + b], f in [0, NIN)   (~4 MB)
__device__ __half g_x16[(size_t)NIN_ * B_];
// hidden activations, transposed uint8: g_act8[(f-NIN) * B + b] (~33.5 MB)
__device__ unsigned char g_act8[(size_t)(L_ * N_) * B_];

// Reordered (byte-offset, weight) lists: fp16-x entries first, int8 after.
// For fp16 entries: off = f * (B_*2), w as-is.
// For int8 entries: off = (f-NIN) * B_, w pre-scaled by 1/255.
__device__ int2 g_iw[(size_t)L_ * N_ * K_];
__device__ int  g_cnt[L_ * N_];
__device__ int2 g_iw_out[NOUT_ * K_];
__device__ int  g_cnt_out[NOUT_];

__device__ __forceinline__ float tanhapx_(float x) {
    float r; asm("tanh.approx.f32 %0, %1;" : "=f"(r) : "f"(x)); return r;
}

// int8 word (4 bytes = 4 batch elems) -> two packed f32x2 FMAs.
// t_i = float bits (0x4B000000 | q_i) = 2^23 + q_i ; debias exactly; acc += w' * q
__device__ __forceinline__ void word_fma2_(unsigned long long& acc01,
                                           unsigned long long& acc23,
                                           unsigned word,
                                           unsigned long long w2,
                                           unsigned long long debias2) {
    asm("{\n\t"
        ".reg .b32 p0, p1, p2, p3;\n\t"
        ".reg .b64 t01, t23;\n\t"
        "prmt.b32 p0, %2, 0x4B000000, 0x7540;\n\t"
        "prmt.b32 p1, %2, 0x4B000000, 0x7541;\n\t"
        "prmt.b32 p2, %2, 0x4B000000, 0x7542;\n\t"
        "prmt.b32 p3, %2, 0x4B000000, 0x7543;\n\t"
        "mov.b64 t01, {p0, p1};\n\t"
        "mov.b64 t23, {p2, p3};\n\t"
        "add.rn.f32x2 t01, t01, %4;\n\t"
        "add.rn.f32x2 t23, t23, %4;\n\t"
        "fma.rn.f32x2 %0, t01, %3, %0;\n\t"
        "fma.rn.f32x2 %1, t23, %3, %1;\n\t"
        "}"
        : "+l"(acc01), "+l"(acc23)
        : "r"(word), "l"(w2), "l"(debias2));
}

// half2 word (2 elems) -> packed f32x2 FMA
__device__ __forceinline__ void h2_fma2_(unsigned long long& acc,
                                         unsigned h2w,
                                         unsigned long long w2) {
    __half2 h = *reinterpret_cast<const __half2*>(&h2w);
    float2 f = __half22float2(h);
    unsigned long long v;
    asm("mov.b64 %0, {%1, %2};" : "=l"(v) : "f"(f.x), "f"(f.y));
    asm("fma.rn.f32x2 %0, %1, %2, %0;" : "+l"(acc) : "l"(v), "l"(w2));
}

__device__ __forceinline__ unsigned long long bcast2_(float w) {
    unsigned long long r;
    asm("mov.b64 %0, {%1, %1};" : "=l"(r) : "f"(w));
    return r;
}

__device__ __forceinline__ float2 unpack2_(unsigned long long p) {
    float2 r;
    asm("mov.b64 {%0, %1}, %2;" : "=f"(r.x), "=f"(r.y) : "l"(p));
    return r;
}

// Shared gather core: 16 batch elems, accumulators acc[8] (packed f32x2).
__device__ __forceinline__ void gather_core_(unsigned long long* acc,
                                             const int2* s_iw_row, int cnt,
                                             int q16, int q32) {
    const unsigned long long debias2 = 0xCB000000CB000000ULL; // {-2^23, -2^23}
    const char* __restrict__ xb = reinterpret_cast<const char*>(g_x16);
    const char* __restrict__ ab = reinterpret_cast<const char*>(g_act8);

    int k = 0;
    // fp16-x entries
#pragma unroll 4
    for (; k < cnt; ++k) {
        const int2 iw = s_iw_row[k];
        const uint4* p = reinterpret_cast<const uint4*>(xb + (unsigned)iw.x + q32);
        uint4 v0 = p[0];
        uint4 v1 = p[1];
        const unsigned long long w2 = bcast2_(__int_as_float(iw.y));
        h2_fma2_(acc[0], v0.x, w2);  h2_fma2_(acc[1], v0.y, w2);
        h2_fma2_(acc[2], v0.z, w2);  h2_fma2_(acc[3], v0.w, w2);
        h2_fma2_(acc[4], v1.x, w2);  h2_fma2_(acc[5], v1.y, w2);
        h2_fma2_(acc[6], v1.z, w2);  h2_fma2_(acc[7], v1.w, w2);
    }
    // int8 entries (w pre-scaled by 1/255)
#pragma unroll 4
    for (; k < K_; ++k) {
        const int2 iw = s_iw_row[k];
        const uint4 v = *reinterpret_cast<const uint4*>(ab + (unsigned)iw.x + q16);
        const unsigned long long w2 = bcast2_(__int_as_float(iw.y));
        word_fma2_(acc[0], acc[1], v.x, w2, debias2);
        word_fma2_(acc[2], acc[3], v.y, w2, debias2);
        word_fma2_(acc[4], acc[5], v.z, w2, debias2);
        word_fma2_(acc[6], acc[7], v.w, w2, debias2);
    }
}

// ---------------------------------------------------------------------------
// Prep: reorder (idx, w) per neuron: fp16 entries first, then int8 entries
// with precomputed byte offsets and w/255 prescale.
// One thread per neuron (L*N hidden + NOUT out).
// ---------------------------------------------------------------------------
__global__ void prep_kernel(const int* __restrict__ idx, const float* __restrict__ W,
                            const int* __restrict__ idx_out, const float* __restrict__ W_out) {
    const int t = blockIdx.x * blockDim.x + threadIdx.x;
    const int* ip;
    const float* wp;
    int2* op;
    int* cp;
    if (t < L_ * N_) {
        ip = idx + (size_t)t * K_;  wp = W + (size_t)t * K_;
        op = g_iw + (size_t)t * K_; cp = g_cnt + t;
    } else if (t < L_ * N_ + NOUT_) {
        const int u = t - L_ * N_;
        ip = idx_out + (size_t)u * K_;  wp = W_out + (size_t)u * K_;
        op = g_iw_out + (size_t)u * K_; cp = g_cnt_out + u;
    } else return;

    int c = 0;
    for (int k = 0; k < K_; ++k) {           // fp16 pass
        const int f = ip[k];
        if (f < NIN_) {
            int2 e; e.x = f * (B_ * 2); e.y = __float_as_int(wp[k]);
            op[c++] = e;
        }
    }
    *cp = c;
    for (int k = 0; k < K_; ++k) {           // int8 pass
        const int f = ip[k];
        if (f >= NIN_) {
            int2 e; e.x = (f - NIN_) * B_; e.y = __float_as_int(wp[k] * (1.0f / 255.0f));
            op[c++] = e;
        }
    }
}

// ---------------------------------------------------------------------------
// Transpose x (B, NIN) f32 row-major -> g_x16[f * B + b] as half
// ---------------------------------------------------------------------------
__global__ void __launch_bounds__(1024) transpose_in_kernel(const float* __restrict__ x) {
    __shared__ float tile[32][33];
    int f0 = blockIdx.x * 32;
    int b0 = blockIdx.y * 32;
    tile[threadIdx.y][threadIdx.x] = x[(size_t)(b0 + threadIdx.y) * NIN_ + (f0 + threadIdx.x)];
    __syncthreads();
    g_x16[(size_t)(f0 + threadIdx.y) * B_ + (b0 + threadIdx.x)] =
        __float2half(tile[threadIdx.x][threadIdx.y]);
}

// ---------------------------------------------------------------------------
// One sparse layer. block (32,8): 8 neurons x 512 batch (16 per thread).
// grid: (8, 64) = 512 blocks.
// ---------------------------------------------------------------------------
__global__ void __launch_bounds__(256, 4) layer_kernel(
    const float* __restrict__ bias,  // (N,) this layer
    int l)
{
    __shared__ int2 s_iw[8][K_];
    __shared__ int  s_cnt[8];
    const int tx = threadIdx.x, ty = threadIdx.y;
    const int n = blockIdx.y * 8 + ty;
    const int gn = l * N_ + n;

    s_iw[ty][tx] = g_iw[(size_t)gn * K_ + tx];
    if (tx == 0) s_cnt[ty] = g_cnt[gn];
    __syncthreads();

    const int q = blockIdx.x * 32 + tx;   // batch chunk [16q, 16q+16)
    const int q16 = q * 16, q32 = q * 32;

    unsigned long long acc[8];
#pragma unroll
    for (int i = 0; i < 8; ++i) acc[i] = 0ull;

    gather_core_(acc, s_iw[ty], s_cnt[ty], q16, q32);

    // epilogue: sigmoid via tanh, quantize to uint8 = round(255*s)
    const float hbb = 0.5f * bias[n];
    unsigned bytes[16];
#pragma unroll
    for (int i = 0; i < 8; ++i) {
        float2 f = unpack2_(acc[i]);
        float t0 = tanhapx_(fmaf(f.x, 0.5f, hbb));
        float t1 = tanhapx_(fmaf(f.y, 0.5f, hbb));
        bytes[2 * i]     = __float2uint_rn(fmaf(t0, 127.5f, 127.5f));
        bytes[2 * i + 1] = __float2uint_rn(fmaf(t1, 127.5f, 127.5f));
    }
    uint4 o;
    unsigned* ow = &o.x;
#pragma unroll
    for (int i = 0; i < 4; ++i) {
        unsigned lo = __byte_perm(bytes[4 * i],     bytes[4 * i + 1], 0x0040);
        unsigned hi = __byte_perm(bytes[4 * i + 2], bytes[4 * i + 3], 0x0040);
        ow[i] = __byte_perm(lo, hi, 0x5410);
    }
    reinterpret_cast<uint4*>(g_act8)[(size_t)gn * (B_ / 16) + q] = o;
}

// ---------------------------------------------------------------------------
// Output layer. block (32,8): 8 neurons x 512 batch (16 per thread).
// grid: (8, 32) = 256 blocks. Exact sigmoid; smem transpose for sector stores.
// ---------------------------------------------------------------------------
__global__ void __launch_bounds__(256, 4) out_kernel(
    const float* __restrict__ b_out,   // (NOUT,)
    float* __restrict__ out)           // (B, NOUT)
{
    __shared__ int2  s_iw[8][K_];
    __shared__ int   s_cnt[8];
    __shared__ float tile[8][512];
    const int tx = threadIdx.x, ty = threadIdx.y;
    const int o0 = blockIdx.y * 8;
    const int o = o0 + ty;

    s_iw[ty][tx] = g_iw_out[(size_t)o * K_ + tx];
    if (tx == 0) s_cnt[ty] = g_cnt_out[o];
    __syncthreads();

    const int q = blockIdx.x * 32 + tx;
    const int q16 = q * 16, q32 = q * 32;

    unsigned long long acc[8];
#pragma unroll
    for (int i = 0; i < 8; ++i) acc[i] = 0ull;

    gather_core_(acc, s_iw[ty], s_cnt[ty], q16, q32);

    const float bb = b_out[o];
    const int bl = tx * 16;
#pragma unroll
    for (int i = 0; i < 8; ++i) {
        float2 f = unpack2_(acc[i]);
        tile[ty][bl + 2 * i]     = 1.0f / (1.0f + __expf(-(f.x + bb)));
        tile[ty][bl + 2 * i + 1] = 1.0f / (1.0f + __expf(-(f.y + bb)));
    }
    __syncthreads();

    const int t = ty * 32 + tx;
    const int bbase = blockIdx.x * 512;
#pragma unroll
    for (int r = 0; r < 2; ++r) {
        const int lb = t + r * 256;
        float4 w0, w1;
        w0.x = tile[0][lb]; w0.y = tile[1][lb]; w0.z = tile[2][lb]; w0.w = tile[3][lb];
        w1.x = tile[4][lb]; w1.y = tile[5][lb]; w1.z = tile[6][lb]; w1.w = tile[7][lb];
        float4* dst = reinterpret_cast<float4*>(out + (size_t)(bbase + lb) * NOUT_ + o0);
        dst[0] = w0;
        dst[1] = w1;
    }
}

// ---------------------------------------------------------------------------
// kernel_launch: inputs in metadata order:
//   0: x (B,NIN) f32   1: W (L,N,K) f32   2: b (L,N) f32
//   3: W_out (NOUT,K) f32   4: b_out (NOUT,) f32
//   5: idx (L,N,K) i32      6: idx_out (NOUT,K) i32
// ---------------------------------------------------------------------------
extern "C" void kernel_launch(void* const* d_in, const int* in_sizes, int n_in,
                              void* d_out, int out_size) {
    const float* x     = (const float*)d_in[0];
    const float* W     = (const float*)d_in[1];
    const float* b     = (const float*)d_in[2];
    const float* W_out = (const float*)d_in[3];
    const float* b_out = (const float*)d_in[4];
    const int*   idx     = (const int*)d_in[5];
    const int*   idx_out = (const int*)d_in[6];
    float* out = (float*)d_out;

    {
        const int nthreads = L_ * N_ + NOUT_;
        prep_kernel<<<(nthreads + 255) / 256, 256>>>(idx, W, idx_out, W_out);
    }
    {
        dim3 blk(32, 32);
        dim3 grd(NIN_ / 32, B_ / 32);
        transpose_in_kernel<<<grd, blk>>>(x);
    }
    {
        dim3 blk(32, 8);
        dim3 grd(8, N_ / 8);
        for (int l = 0; l < L_; ++l) {
            layer_kernel<<<grd, blk>>>(b + (size_t)l * N_, l);
        }
    }
    {
        dim3 blk(32, 8);
        dim3 grd(8, NOUT_ / 8);
        out_kernel<<<grd, blk>>>(b_out, out);
    }
}

// round 7
// speedup vs baseline: 1.4230x; 1.0870x over previous
#include <cuda_runtime.h>
#include <cstddef>

// Problem constants (fixed by the reference)
#define B_    4096
#define NIN_  512
#define L_    16
#define N_    512
#define K_    32
#define NOUT_ 256
#define NNEUR_ (L_ * N_ + NOUT_)      // 8448 total neurons
#define MAXG_  16                     // max groups/neuron (<= 64 entries / 4)

// Unified byte buffer, feature-major rows of B_ bytes:
//   rows [0, 512):        x hi-plane  (u16 value >> 8)
//   rows [512, 1024):     x lo-plane  (u16 value & 0xFF)
//   rows [1024, 9216):    hidden activations u8 = round(255*sigmoid)
#define NROWS_ (2 * NIN_ + L_ * N_)   // 9216
__device__ unsigned char g_bytes[(size_t)NROWS_ * B_];

// Per-neuron preprocessed tables (prep_kernel fills these)
__device__ int4  g_offs [(size_t)NNEUR_ * MAXG_];  // 4 byte-offsets per group
__device__ int2  g_wpk  [(size_t)NNEUR_ * MAXG_];  // packed s16x2 weights (lo,hi)
__device__ int   g_ng   [NNEUR_];                  // group count
__device__ float g_scale[NNEUR_];                  // s/32767
__device__ float g_badj [NNEUR_];                  // bias + offset correction

__device__ __forceinline__ float tanhapx_(float x) {
    float r; asm("tanh.approx.f32 %0, %1;" : "=f"(r) : "f"(x)); return r;
}
__device__ __forceinline__ unsigned prmt_(unsigned a, unsigned b, unsigned sel) {
    unsigned d; asm("prmt.b32 %0, %1, %2, %3;" : "=r"(d) : "r"(a), "r"(b), "r"(sel));
    return d;
}
__device__ __forceinline__ void dp2a_lo_(int& acc, int a, unsigned b) {
    asm("dp2a.lo.s32.u32 %0, %1, %2, %0;" : "+r"(acc) : "r"(a), "r"(b));
}
__device__ __forceinline__ void dp2a_hi_(int& acc, int a, unsigned b) {
    asm("dp2a.hi.s32.u32 %0, %1, %2, %0;" : "+r"(acc) : "r"(a), "r"(b));
}

// 4x4 byte transpose (A,B,C,D = 4 feature words, 4 batch bytes each) + dp2a.
// After transpose, word for batch elem j has bytes (k0,k1,k2,k3).
__device__ __forceinline__ void tblock_(int* acc, unsigned A, unsigned Bw,
                                        unsigned C, unsigned D, int wlo, int whi) {
    unsigned t0 = prmt_(A, Bw, 0x5140u);   // A0,B0,A1,B1
    unsigned t1 = prmt_(C, D,  0x5140u);   // C0,D0,C1,D1
    unsigned t2 = prmt_(A, Bw, 0x7362u);   // A2,B2,A3,B3
    unsigned t3 = prmt_(C, D,  0x7362u);   // C2,D2,C3,D3
    unsigned b0 = prmt_(t0, t1, 0x5410u);  // A0,B0,C0,D0
    unsigned b1 = prmt_(t0, t1, 0x7632u);  // A1,B1,C1,D1
    unsigned b2 = prmt_(t2, t3, 0x5410u);  // A2,B2,C2,D2
    unsigned b3 = prmt_(t2, t3, 0x7632u);  // A3,B3,C3,D3
    dp2a_lo_(acc[0], wlo, b0); dp2a_hi_(acc[0], whi, b0);
    dp2a_lo_(acc[1], wlo, b1); dp2a_hi_(acc[1], whi, b1);
    dp2a_lo_(acc[2], wlo, b2); dp2a_hi_(acc[2], whi, b2);
    dp2a_lo_(acc[3], wlo, b3); dp2a_hi_(acc[3], whi, b3);
}

// Gather core: 16 batch elems (byte offset q16), int32 accumulators iacc[16].
__device__ __forceinline__ void gather_i8_(int* iacc, const int4* s_offs,
                                           const int2* s_wpk, int ng, int q16) {
    const char* __restrict__ gb = reinterpret_cast<const char*>(g_bytes);
    for (int g = 0; g < ng; ++g) {
        const int4 of = s_offs[g];
        const int2 wp = s_wpk[g];
        const uint4 v0 = *reinterpret_cast<const uint4*>(gb + of.x + q16);
        const uint4 v1 = *reinterpret_cast<const uint4*>(gb + of.y + q16);
        const uint4 v2 = *reinterpret_cast<const uint4*>(gb + of.z + q16);
        const uint4 v3 = *reinterpret_cast<const uint4*>(gb + of.w + q16);
        tblock_(iacc + 0,  v0.x, v1.x, v2.x, v3.x, wp.x, wp.y);
        tblock_(iacc + 4,  v0.y, v1.y, v2.y, v3.y, wp.x, wp.y);
        tblock_(iacc + 8,  v0.z, v1.z, v2.z, v3.z, wp.x, wp.y);
        tblock_(iacc + 12, v0.w, v1.w, v2.w, v3.w, wp.x, wp.y);
    }
}

// ---------------------------------------------------------------------------
// Prep: per neuron, expand entries (x -> hi+lo planes), fold plane constants
// into s16 weight codes with per-neuron scale, pack into groups of 4.
// ---------------------------------------------------------------------------
__global__ void prep_kernel(const int* __restrict__ idx, const float* __restrict__ W,
                            const float* __restrict__ b,
                            const int* __restrict__ idx_out, const float* __restrict__ W_out,
                            const float* __restrict__ b_out) {
    const int t = blockIdx.x * blockDim.x + threadIdx.x;
    if (t >= NNEUR_) return;
    const int* ip; const float* wp; float bias;
    if (t < L_ * N_) { ip = idx + (size_t)t * K_;  wp = W + (size_t)t * K_;  bias = b[t]; }
    else { const int u = t - L_ * N_;
           ip = idx_out + (size_t)u * K_;  wp = W_out + (size_t)u * K_;  bias = b_out[u]; }

    int   eoff[2 * K_];
    float ecf [2 * K_];
    int ne = 0;
    float corr = 0.f;
    for (int k = 0; k < K_; ++k) {
        const int f = ip[k];
        const float w = wp[k];
        if (f < NIN_) {
            eoff[ne] = f * B_;             ecf[ne++] = w * (1.0f / 16.0f);    // hi plane
            eoff[ne] = (NIN_ + f) * B_;    ecf[ne++] = w * (1.0f / 4096.0f);  // lo plane
            corr -= 8.0f * w;
        } else {
            eoff[ne] = (2 * NIN_ + (f - NIN_)) * B_;  ecf[ne++] = w * (1.0f / 255.0f);
        }
    }
    float s = 0.f;
    for (int i = 0; i < ne; ++i) s = fmaxf(s, fabsf(ecf[i]));
    if (s == 0.f) s = 1.f;
    const float inv = 32767.0f / s;
    while (ne & 3) { eoff[ne] = 0; ecf[ne] = 0.f; ++ne; }
    const int ng = ne >> 2;
    for (int g = 0; g < ng; ++g) {
        int4 o4;
        o4.x = eoff[4 * g];     o4.y = eoff[4 * g + 1];
        o4.z = eoff[4 * g + 2]; o4.w = eoff[4 * g + 3];
        int q[4];
#pragma unroll
        for (int j = 0; j < 4; ++j) {
            int v = __float2int_rn(ecf[4 * g + j] * inv);
            q[j] = max(-32767, min(32767, v));
        }
        int2 wpk;
        wpk.x = (q[1] << 16) | (q[0] & 0xFFFF);
        wpk.y = (q[3] << 16) | (q[2] & 0xFFFF);
        g_offs[(size_t)t * MAXG_ + g] = o4;
        g_wpk [(size_t)t * MAXG_ + g] = wpk;
    }
    g_ng[t]    = ng;
    g_scale[t] = s / 32767.0f;
    g_badj[t]  = bias + corr;
}

// ---------------------------------------------------------------------------
// Transpose x (B, NIN) f32 -> two u8 planes (feature-major), u16 = (x+8)*4096
// ---------------------------------------------------------------------------
__global__ void __launch_bounds__(1024) transpose_in_kernel(const float* __restrict__ x) {
    __shared__ float tile[32][33];
    const int f0 = blockIdx.x * 32;
    const int b0 = blockIdx.y * 32;
    tile[threadIdx.y][threadIdx.x] = x[(size_t)(b0 + threadIdx.y) * NIN_ + (f0 + threadIdx.x)];
    __syncthreads();
    const float xv = tile[threadIdx.x][threadIdx.y];
    float vf = fminf(fmaxf((xv + 8.0f) * 4096.0f, 0.0f), 65535.0f);
    const unsigned u = __float2uint_rn(vf);
    const int f = f0 + threadIdx.y;
    const int bb = b0 + threadIdx.x;
    g_bytes[(size_t)f * B_ + bb]           = (unsigned char)(u >> 8);
    g_bytes[(size_t)(NIN_ + f) * B_ + bb]  = (unsigned char)(u & 0xFF);
}

// ---------------------------------------------------------------------------
// One sparse layer. block (32,8): warp = one neuron, 32 tx x 16 batch = 512.
// grid (8, 64) = 512 blocks.
// ---------------------------------------------------------------------------
__global__ void __launch_bounds__(256, 4) layer_kernel(int l) {
    __shared__ int4  s_offs[8][MAXG_];
    __shared__ int2  s_wpk [8][MAXG_];
    __shared__ int   s_ng[8];
    __shared__ float s_sc[8], s_ba[8];
    const int tx = threadIdx.x, ty = threadIdx.y;
    const int n  = blockIdx.y * 8 + ty;
    const int gn = l * N_ + n;

    if (tx < MAXG_)            s_offs[ty][tx]         = g_offs[(size_t)gn * MAXG_ + tx];
    else if (tx < 2 * MAXG_)   s_wpk [ty][tx - MAXG_] = g_wpk [(size_t)gn * MAXG_ + (tx - MAXG_)];
    if (tx == 0) { s_ng[ty] = g_ng[gn]; s_sc[ty] = g_scale[gn]; s_ba[ty] = g_badj[gn]; }
    __syncthreads();

    const int q16 = (blockIdx.x * 32 + tx) * 16;

    int iacc[16];
#pragma unroll
    for (int i = 0; i < 16; ++i) iacc[i] = 0;

    gather_i8_(iacc, s_offs[ty], s_wpk[ty], s_ng[ty], q16);

    const float sc = s_sc[ty];
    const float ba = s_ba[ty];
    unsigned bytes[16];
#pragma unroll
    for (int i = 0; i < 16; ++i) {
        const float pre = fmaf((float)iacc[i], sc, ba);
        const float th  = tanhapx_(0.5f * pre);                 // sigmoid = .5+.5*tanh(v/2)
        bytes[i] = __float2uint_rn(fmaf(th, 127.5f, 127.5f));   // round(255*sigmoid)
    }
    uint4 o;
    unsigned* ow = &o.x;
#pragma unroll
    for (int i = 0; i < 4; ++i) {
        unsigned lo = __byte_perm(bytes[4 * i],     bytes[4 * i + 1], 0x0040);
        unsigned hi = __byte_perm(bytes[4 * i + 2], bytes[4 * i + 3], 0x0040);
        ow[i] = __byte_perm(lo, hi, 0x5410);
    }
    *reinterpret_cast<uint4*>(g_bytes + (size_t)(2 * NIN_ + gn) * B_ + q16) = o;
}

// ---------------------------------------------------------------------------
// Output layer. block (32,8), grid (8, 32). Exact sigmoid, f32 out,
// smem transpose so each thread stores full 32B sectors.
// ---------------------------------------------------------------------------
__global__ void __launch_bounds__(256, 4) out_kernel(float* __restrict__ out) {
    __shared__ int4  s_offs[8][MAXG_];
    __shared__ int2  s_wpk [8][MAXG_];
    __shared__ int   s_ng[8];
    __shared__ float s_sc[8], s_ba[8];
    __shared__ float tile[8][512];
    const int tx = threadIdx.x, ty = threadIdx.y;
    const int o0 = blockIdx.y * 8;
    const int o  = o0 + ty;
    const int gn = L_ * N_ + o;

    if (tx < MAXG_)            s_offs[ty][tx]         = g_offs[(size_t)gn * MAXG_ + tx];
    else if (tx < 2 * MAXG_)   s_wpk [ty][tx - MAXG_] = g_wpk [(size_t)gn * MAXG_ + (tx - MAXG_)];
    if (tx == 0) { s_ng[ty] = g_ng[gn]; s_sc[ty] = g_scale[gn]; s_ba[ty] = g_badj[gn]; }
    __syncthreads();

    const int q16 = (blockIdx.x * 32 + tx) * 16;

    int iacc[16];
#pragma unroll
    for (int i = 0; i < 16; ++i) iacc[i] = 0;

    gather_i8_(iacc, s_offs[ty], s_wpk[ty], s_ng[ty], q16);

    const float sc = s_sc[ty];
    const float ba = s_ba[ty];
    const int bl = tx * 16;
#pragma unroll
    for (int i = 0; i < 16; ++i) {
        const float pre = fmaf((float)iacc[i], sc, ba);
        tile[ty][bl + i] = 1.0f / (1.0f + __expf(-pre));
    }
    __syncthreads();

    const int t = ty * 32 + tx;
    const int bbase = blockIdx.x * 512;
#pragma unroll
    for (int r = 0; r < 2; ++r) {
        const int lb = t + r * 256;
        float4 w0, w1;
        w0.x = tile[0][lb]; w0.y = tile[1][lb]; w0.z = tile[2][lb]; w0.w = tile[3][lb];
        w1.x = tile[4][lb]; w1.y = tile[5][lb]; w1.z = tile[6][lb]; w1.w = tile[7][lb];
        float4* dst = reinterpret_cast<float4*>(out + (size_t)(bbase + lb) * NOUT_ + o0);
        dst[0] = w0;
        dst[1] = w1;
    }
}

// ---------------------------------------------------------------------------
// kernel_launch: inputs in metadata order:
//   0: x (B,NIN) f32   1: W (L,N,K) f32   2: b (L,N) f32
//   3: W_out (NOUT,K) f32   4: b_out (NOUT,) f32
//   5: idx (L,N,K) i32      6: idx_out (NOUT,K) i32
// ---------------------------------------------------------------------------
extern "C" void kernel_launch(void* const* d_in, const int* in_sizes, int n_in,
                              void* d_out, int out_size) {
    const float* x     = (const float*)d_in[0];
    const float* W     = (const float*)d_in[1];
    const float* b     = (const float*)d_in[2];
    const float* W_out = (const float*)d_in[3];
    const float* b_out = (const float*)d_in[4];
    const int*   idx     = (const int*)d_in[5];
    const int*   idx_out = (const int*)d_in[6];
    float* out = (float*)d_out;

    prep_kernel<<<(NNEUR_ + 255) / 256, 256>>>(idx, W, b, idx_out, W_out, b_out);
    {
        dim3 blk(32, 32);
        dim3 grd(NIN_ / 32, B_ / 32);
        transpose_in_kernel<<<grd, blk>>>(x);
    }
    {
        dim3 blk(32, 8);
        dim3 grd(8, N_ / 8);
        for (int l = 0; l < L_; ++l) layer_kernel<<<grd, blk>>>(l);
    }
    {
        dim3 blk(32, 8);
        dim3 grd(8, NOUT_ / 8);
        out_kernel<<<grd, blk>>>(out);
    }
}